// round 1
// baseline (speedup 1.0000x reference)
#include <cuda_runtime.h>
#include <cuda_bf16.h>
#include <cstdint>
#include <cstdio>

#define N_DIM 8192
#define M_DIM 16384
#define D_DIM 256

#define BM 128
#define BN 128
#define BK 64
#define KT (D_DIM / BK)   // 4 k-tiles
#define THREADS 256

#define STAGE_BYTES 32768  // A(16KB) + B(16KB)
#define A_OFF 0
#define B_OFF 16384
#define SMEM_TOTAL (2 * STAGE_BYTES)

// -------- scratch (no allocations allowed) --------
__device__ __nv_bfloat16 g_u[(size_t)N_DIM * D_DIM];
__device__ __nv_bfloat16 g_i[(size_t)M_DIM * D_DIM];
__device__ double g_acc;

// -------- tiny helpers --------
__device__ __forceinline__ void cp_async16(uint32_t dst, const void* src) {
    asm volatile("cp.async.cg.shared.global [%0], [%1], 16;\n" :: "r"(dst), "l"(src));
}
__device__ __forceinline__ void cp_commit() {
    asm volatile("cp.async.commit_group;\n" ::: "memory");
}
template <int n>
__device__ __forceinline__ void cp_wait() {
    asm volatile("cp.async.wait_group %0;\n" :: "n"(n) : "memory");
}
__device__ __forceinline__ void ldsm_x4(uint32_t& r0, uint32_t& r1, uint32_t& r2,
                                        uint32_t& r3, uint32_t addr) {
    asm volatile("ldmatrix.sync.aligned.m8n8.x4.shared.b16 {%0,%1,%2,%3}, [%4];\n"
                 : "=r"(r0), "=r"(r1), "=r"(r2), "=r"(r3)
                 : "r"(addr));
}
__device__ __forceinline__ void mma16816(float c[4],
                                         uint32_t a0, uint32_t a1, uint32_t a2, uint32_t a3,
                                         uint32_t b0, uint32_t b1) {
    asm volatile(
        "mma.sync.aligned.m16n8k16.row.col.f32.bf16.bf16.f32 "
        "{%0,%1,%2,%3},{%4,%5,%6,%7},{%8,%9},{%0,%1,%2,%3};\n"
        : "+f"(c[0]), "+f"(c[1]), "+f"(c[2]), "+f"(c[3])
        : "r"(a0), "r"(a1), "r"(a2), "r"(a3), "r"(b0), "r"(b1));
}

// -------- init --------
__global__ void init_kernel() { g_acc = 0.0; }

// -------- fp32 -> bf16 convert fused with  lam * sum(||row||) --------
__device__ __forceinline__ void conv_norm_body(const float* __restrict__ src,
                                               __nv_bfloat16* __restrict__ dst,
                                               float lam) {
    const int row = blockIdx.x;
    const int tid = threadIdx.x;  // 128 threads, D=256 -> 2 elems each
    const float* s = src + (size_t)row * D_DIM;
    __nv_bfloat16* d = dst + (size_t)row * D_DIM;
    float v0 = s[tid];
    float v1 = s[tid + 128];
    d[tid] = __float2bfloat16(v0);
    d[tid + 128] = __float2bfloat16(v1);
    float ss = v0 * v0 + v1 * v1;
#pragma unroll
    for (int o = 16; o; o >>= 1) ss += __shfl_xor_sync(0xffffffffu, ss, o);
    __shared__ float red[4];
    if ((tid & 31) == 0) red[tid >> 5] = ss;
    __syncthreads();
    if (tid == 0) {
        float t = red[0] + red[1] + red[2] + red[3];
        atomicAdd(&g_acc, (double)(lam * sqrtf(t)));
    }
}
__global__ void conv_u_kernel(const float* __restrict__ src) {
    conv_norm_body(src, g_u, 0.1f);
}
__global__ void conv_i_kernel(const float* __restrict__ src) {
    conv_norm_body(src, g_i, 0.1f);
}

// -------- main fused GEMM + masked-SSE --------
__global__ __launch_bounds__(THREADS, 2)
void pmf_main(const float* __restrict__ rating, const float* __restrict__ mask) {
    extern __shared__ char smem[];
    const int tid = threadIdx.x;
    const int lane = tid & 31;
    const int wid = tid >> 5;          // 8 warps
    const int warp_m = wid >> 2;       // 0..1  (64-row strip within tile)
    const int warp_n = wid & 3;        // 0..3  (32-col strip within tile)

    const int row0 = blockIdx.y * BM;  // index into N (u rows)
    const int col0 = blockIdx.x * BN;  // index into M (i rows)

    const uint32_t smem_base = (uint32_t)__cvta_generic_to_shared(smem);
    const __nv_bfloat16* Ag = g_u + (size_t)row0 * D_DIM;
    const __nv_bfloat16* Bg = g_i + (size_t)col0 * D_DIM;

    float acc[4][4][4];
#pragma unroll
    for (int i = 0; i < 4; ++i)
#pragma unroll
        for (int j = 0; j < 4; ++j)
#pragma unroll
            for (int k = 0; k < 4; ++k) acc[i][j][k] = 0.f;

    // --- loader geometry (each thread moves 16B chunks; 128B rows, xor-swizzled) ---
    const int lrow = tid >> 3;  // 0..31
    const int lch = tid & 7;    // 16B chunk within row

    auto load_tile = [&](int kt, int s) {
        const uint32_t sa = smem_base + (uint32_t)s * STAGE_BYTES;
#pragma unroll
        for (int it = 0; it < 4; ++it) {
            int row = lrow + it * 32;
            uint32_t d = sa + A_OFF + row * 128 + (uint32_t)((lch ^ (row & 7)) << 4);
            cp_async16(d, Ag + (size_t)row * D_DIM + kt * BK + lch * 8);
        }
#pragma unroll
        for (int it = 0; it < 4; ++it) {
            int row = lrow + it * 32;
            uint32_t d = sa + B_OFF + row * 128 + (uint32_t)((lch ^ (row & 7)) << 4);
            cp_async16(d, Bg + (size_t)row * D_DIM + kt * BK + lch * 8);
        }
        cp_commit();
    };

    // --- ldmatrix lane geometry ---
    const int q = lane >> 3;    // which 8x8 matrix this lane addresses
    const int r8 = lane & 7;

    auto compute_tile = [&](int s) {
        const uint32_t sa = smem_base + (uint32_t)s * STAGE_BYTES;
#pragma unroll
        for (int ks = 0; ks < 4; ++ks) {  // 4 k16 steps per 64-wide k-tile
            uint32_t a[4][4];
#pragma unroll
            for (int mf = 0; mf < 4; ++mf) {
                int arow = warp_m * 64 + mf * 16 + (q & 1) * 8 + r8;
                int ch = ks * 2 + (q >> 1);
                uint32_t addr = sa + A_OFF + arow * 128 +
                                (uint32_t)((ch ^ (arow & 7)) << 4);
                ldsm_x4(a[mf][0], a[mf][1], a[mf][2], a[mf][3], addr);
            }
            uint32_t b[4][2];
#pragma unroll
            for (int nf2 = 0; nf2 < 2; ++nf2) {
                int brow = warp_n * 32 + nf2 * 16 + (q >> 1) * 8 + r8;
                int ch = ks * 2 + (q & 1);
                uint32_t addr = sa + B_OFF + brow * 128 +
                                (uint32_t)((ch ^ (brow & 7)) << 4);
                uint32_t r0, r1, r2, r3;
                ldsm_x4(r0, r1, r2, r3, addr);
                b[nf2 * 2][0] = r0;
                b[nf2 * 2][1] = r1;
                b[nf2 * 2 + 1][0] = r2;
                b[nf2 * 2 + 1][1] = r3;
            }
#pragma unroll
            for (int mf = 0; mf < 4; ++mf)
#pragma unroll
                for (int nf = 0; nf < 4; ++nf)
                    mma16816(acc[mf][nf], a[mf][0], a[mf][1], a[mf][2], a[mf][3],
                             b[nf][0], b[nf][1]);
        }
    };

    // --- 2-stage pipelined mainloop over D ---
    load_tile(0, 0);
#pragma unroll
    for (int kt = 0; kt < KT; ++kt) {
        if (kt + 1 < KT) {
            load_tile(kt + 1, (kt + 1) & 1);
            cp_wait<1>();
        } else {
            cp_wait<0>();
        }
        __syncthreads();
        compute_tile(kt & 1);
        __syncthreads();
    }

    // --- epilogue: stream rating/mask, masked squared error ---
    float loss = 0.f;
    const int lrow4 = lane >> 2;
    const int lcol2 = (lane & 3) * 2;
#pragma unroll
    for (int mf = 0; mf < 4; ++mf) {
        int gr0 = row0 + warp_m * 64 + mf * 16 + lrow4;
#pragma unroll
        for (int nf = 0; nf < 4; ++nf) {
            int gc = col0 + warp_n * 32 + nf * 8 + lcol2;
            size_t off0 = (size_t)gr0 * M_DIM + gc;
            size_t off1 = off0 + (size_t)8 * M_DIM;
            float2 rv0 = *(const float2*)(rating + off0);
            float2 mv0 = *(const float2*)(mask + off0);
            float2 rv1 = *(const float2*)(rating + off1);
            float2 mv1 = *(const float2*)(mask + off1);
            float d0 = rv0.x - acc[mf][nf][0];
            float d1 = rv0.y - acc[mf][nf][1];
            float d2 = rv1.x - acc[mf][nf][2];
            float d3 = rv1.y - acc[mf][nf][3];
            loss += d0 * d0 * mv0.x;
            loss += d1 * d1 * mv0.y;
            loss += d2 * d2 * mv1.x;
            loss += d3 * d3 * mv1.y;
        }
    }
#pragma unroll
    for (int o = 16; o; o >>= 1) loss += __shfl_xor_sync(0xffffffffu, loss, o);
    __shared__ float red[8];
    if (lane == 0) red[wid] = loss;
    __syncthreads();
    if (tid == 0) {
        float s = 0.f;
#pragma unroll
        for (int w = 0; w < 8; ++w) s += red[w];
        atomicAdd(&g_acc, (double)s);
    }
}

// -------- finalize --------
__global__ void finalize_kernel(float* out) { out[0] = (float)g_acc; }

extern "C" void kernel_launch(void* const* d_in, const int* in_sizes, int n_in,
                              void* d_out, int out_size) {
    const float* rating = (const float*)d_in[0];
    const float* u_mat = (const float*)d_in[1];
    const float* i_mat = (const float*)d_in[2];
    const float* mask = (const float*)d_in[3];
    float* out = (float*)d_out;

    cudaFuncSetAttribute(pmf_main, cudaFuncAttributeMaxDynamicSharedMemorySize,
                         SMEM_TOTAL);

    init_kernel<<<1, 1>>>();
    conv_u_kernel<<<N_DIM, 128>>>(u_mat);
    conv_i_kernel<<<M_DIM, 128>>>(i_mat);

    dim3 grid(M_DIM / BN, N_DIM / BM);  // 128 x 64 = 8192 CTAs
    pmf_main<<<grid, THREADS, SMEM_TOTAL>>>(rating, mask);

    finalize_kernel<<<1, 1>>>(out);
}

// round 2
// speedup vs baseline: 1.0613x; 1.0613x over previous
#include <cuda_runtime.h>
#include <cuda_bf16.h>
#include <cstdint>

#define N_DIM 8192
#define M_DIM 16384
#define D_DIM 256

#define BM 128
#define BN 128
#define BK 64
#define KT (D_DIM / BK)   // 4 k-tiles
#define THREADS 256

#define STAGE_BYTES 32768  // A(16KB) + B(16KB)
#define A_OFF 0
#define B_OFF 16384
#define SMEM_TOTAL (2 * STAGE_BYTES)

// -------- scratch (no allocations allowed) --------
__device__ __nv_bfloat16 g_u[(size_t)N_DIM * D_DIM];
__device__ __nv_bfloat16 g_i[(size_t)M_DIM * D_DIM];
__device__ double g_acc;

// -------- tiny helpers --------
__device__ __forceinline__ void cp_async16(uint32_t dst, const void* src) {
    asm volatile("cp.async.cg.shared.global [%0], [%1], 16;\n" :: "r"(dst), "l"(src));
}
__device__ __forceinline__ void cp_commit() {
    asm volatile("cp.async.commit_group;\n" ::: "memory");
}
template <int n>
__device__ __forceinline__ void cp_wait() {
    asm volatile("cp.async.wait_group %0;\n" :: "n"(n) : "memory");
}
__device__ __forceinline__ void prefetch_l2(const void* p) {
    asm volatile("prefetch.global.L2 [%0];\n" :: "l"(p));
}
__device__ __forceinline__ void ldsm_x4(uint32_t& r0, uint32_t& r1, uint32_t& r2,
                                        uint32_t& r3, uint32_t addr) {
    asm volatile("ldmatrix.sync.aligned.m8n8.x4.shared.b16 {%0,%1,%2,%3}, [%4];\n"
                 : "=r"(r0), "=r"(r1), "=r"(r2), "=r"(r3)
                 : "r"(addr));
}
__device__ __forceinline__ void mma16816(float c[4],
                                         uint32_t a0, uint32_t a1, uint32_t a2, uint32_t a3,
                                         uint32_t b0, uint32_t b1) {
    asm volatile(
        "mma.sync.aligned.m16n8k16.row.col.f32.bf16.bf16.f32 "
        "{%0,%1,%2,%3},{%4,%5,%6,%7},{%8,%9},{%0,%1,%2,%3};\n"
        : "+f"(c[0]), "+f"(c[1]), "+f"(c[2]), "+f"(c[3])
        : "r"(a0), "r"(a1), "r"(a2), "r"(a3), "r"(b0), "r"(b1));
}

// -------- init --------
__global__ void init_kernel() { g_acc = 0.0; }

// -------- fused fp32->bf16 convert + lam*sum(||row||), one warp per row --------
// grid covers N_DIM + M_DIM rows, 8 rows per block (256 threads).
__global__ void conv_kernel(const float* __restrict__ u_mat,
                            const float* __restrict__ i_mat) {
    const int lane = threadIdx.x & 31;
    const int wrp = threadIdx.x >> 5;
    const int row = blockIdx.x * 8 + wrp;

    const float* src;
    __nv_bfloat16* dst;
    if (row < N_DIM) {
        src = u_mat + (size_t)row * D_DIM;
        dst = g_u + (size_t)row * D_DIM;
    } else {
        src = i_mat + (size_t)(row - N_DIM) * D_DIM;
        dst = g_i + (size_t)(row - N_DIM) * D_DIM;
    }

    float4 v0 = *(const float4*)(src + lane * 4);
    float4 v1 = *(const float4*)(src + 128 + lane * 4);

    __nv_bfloat162 p0 = {__float2bfloat16(v0.x), __float2bfloat16(v0.y)};
    __nv_bfloat162 p1 = {__float2bfloat16(v0.z), __float2bfloat16(v0.w)};
    __nv_bfloat162 p2 = {__float2bfloat16(v1.x), __float2bfloat16(v1.y)};
    __nv_bfloat162 p3 = {__float2bfloat16(v1.z), __float2bfloat16(v1.w)};
    ((__nv_bfloat162*)(dst))[lane * 2] = p0;
    ((__nv_bfloat162*)(dst))[lane * 2 + 1] = p1;
    ((__nv_bfloat162*)(dst + 128))[lane * 2] = p2;
    ((__nv_bfloat162*)(dst + 128))[lane * 2 + 1] = p3;

    float ss = v0.x * v0.x + v0.y * v0.y + v0.z * v0.z + v0.w * v0.w +
               v1.x * v1.x + v1.y * v1.y + v1.z * v1.z + v1.w * v1.w;
#pragma unroll
    for (int o = 16; o; o >>= 1) ss += __shfl_xor_sync(0xffffffffu, ss, o);

    __shared__ float red[8];
    if (lane == 0) red[wrp] = 0.1f * sqrtf(ss);
    __syncthreads();
    if (threadIdx.x == 0) {
        float s = 0.f;
#pragma unroll
        for (int w = 0; w < 8; ++w) s += red[w];
        atomicAdd(&g_acc, (double)s);
    }
}

// -------- main fused GEMM + masked-SSE --------
__global__ __launch_bounds__(THREADS, 2)
void pmf_main(const float* __restrict__ rating, const float* __restrict__ mask) {
    extern __shared__ char smem[];
    const int tid = threadIdx.x;
    const int lane = tid & 31;
    const int wid = tid >> 5;          // 8 warps
    const int warp_m = wid >> 2;       // 0..1  (64-row strip within tile)
    const int warp_n = wid & 3;        // 0..3  (32-col strip within tile)

    const int row0 = blockIdx.y * BM;  // index into N (u rows)
    const int col0 = blockIdx.x * BN;  // index into M (i rows)

    const uint32_t smem_base = (uint32_t)__cvta_generic_to_shared(smem);
    const __nv_bfloat16* Ag = g_u + (size_t)row0 * D_DIM;
    const __nv_bfloat16* Bg = g_i + (size_t)col0 * D_DIM;

    float acc[4][4][4];
#pragma unroll
    for (int i = 0; i < 4; ++i)
#pragma unroll
        for (int j = 0; j < 4; ++j)
#pragma unroll
            for (int k = 0; k < 4; ++k) acc[i][j][k] = 0.f;

    // --- loader geometry (each thread moves 16B chunks; 128B rows, xor-swizzled) ---
    const int lrow = tid >> 3;  // 0..31
    const int lch = tid & 7;    // 16B chunk within row

    auto load_tile = [&](int kt, int s) {
        const uint32_t sa = smem_base + (uint32_t)s * STAGE_BYTES;
#pragma unroll
        for (int it = 0; it < 4; ++it) {
            int row = lrow + it * 32;
            uint32_t d = sa + A_OFF + row * 128 + (uint32_t)((lch ^ (row & 7)) << 4);
            cp_async16(d, Ag + (size_t)row * D_DIM + kt * BK + lch * 8);
        }
#pragma unroll
        for (int it = 0; it < 4; ++it) {
            int row = lrow + it * 32;
            uint32_t d = sa + B_OFF + row * 128 + (uint32_t)((lch ^ (row & 7)) << 4);
            cp_async16(d, Bg + (size_t)row * D_DIM + kt * BK + lch * 8);
        }
        cp_commit();
    };

    // Kick off GEMM pipeline first, then blast L2 prefetches for this CTA's
    // rating/mask tile so the DRAM fetch overlaps the whole MMA mainloop.
    load_tile(0, 0);
    {
        const float* rbase = rating + (size_t)row0 * M_DIM + col0;
        const float* mbase = mask + (size_t)row0 * M_DIM + col0;
        // 128 rows x 512 B = 512 lines of 128 B per array; 2 per thread per array
#pragma unroll
        for (int i = 0; i < 2; ++i) {
            int idx = tid + i * THREADS;      // 0..511
            int r = idx >> 2;
            int c = (idx & 3) << 5;           // 0,32,64,96 floats
            prefetch_l2(rbase + (size_t)r * M_DIM + c);
            prefetch_l2(mbase + (size_t)r * M_DIM + c);
        }
    }

    // --- ldmatrix lane geometry ---
    const int q = lane >> 3;    // which 8x8 matrix this lane addresses
    const int r8 = lane & 7;

    auto compute_tile = [&](int s) {
        const uint32_t sa = smem_base + (uint32_t)s * STAGE_BYTES;
#pragma unroll
        for (int ks = 0; ks < 4; ++ks) {  // 4 k16 steps per 64-wide k-tile
            uint32_t a[4][4];
#pragma unroll
            for (int mf = 0; mf < 4; ++mf) {
                int arow = warp_m * 64 + mf * 16 + (q & 1) * 8 + r8;
                int ch = ks * 2 + (q >> 1);
                uint32_t addr = sa + A_OFF + arow * 128 +
                                (uint32_t)((ch ^ (arow & 7)) << 4);
                ldsm_x4(a[mf][0], a[mf][1], a[mf][2], a[mf][3], addr);
            }
            uint32_t b[4][2];
#pragma unroll
            for (int nf2 = 0; nf2 < 2; ++nf2) {
                int brow = warp_n * 32 + nf2 * 16 + (q >> 1) * 8 + r8;
                int ch = ks * 2 + (q & 1);
                uint32_t addr = sa + B_OFF + brow * 128 +
                                (uint32_t)((ch ^ (brow & 7)) << 4);
                uint32_t r0, r1, r2, r3;
                ldsm_x4(r0, r1, r2, r3, addr);
                b[nf2 * 2][0] = r0;
                b[nf2 * 2][1] = r1;
                b[nf2 * 2 + 1][0] = r2;
                b[nf2 * 2 + 1][1] = r3;
            }
#pragma unroll
            for (int mf = 0; mf < 4; ++mf)
#pragma unroll
                for (int nf = 0; nf < 4; ++nf)
                    mma16816(acc[mf][nf], a[mf][0], a[mf][1], a[mf][2], a[mf][3],
                             b[nf][0], b[nf][1]);
        }
    };

    // --- 2-stage pipelined mainloop over D ---
#pragma unroll
    for (int kt = 0; kt < KT; ++kt) {
        if (kt + 1 < KT) {
            load_tile(kt + 1, (kt + 1) & 1);
            cp_wait<1>();
        } else {
            cp_wait<0>();
        }
        __syncthreads();
        compute_tile(kt & 1);
        __syncthreads();
    }

    // --- epilogue: stream rating/mask (L2-hot from prefetch), masked SSE ---
    float loss = 0.f;
    const int lrow4 = lane >> 2;
    const int lcol2 = (lane & 3) * 2;
#pragma unroll
    for (int mf = 0; mf < 4; ++mf) {
        int gr0 = row0 + warp_m * 64 + mf * 16 + lrow4;
#pragma unroll
        for (int nf = 0; nf < 4; ++nf) {
            int gc = col0 + warp_n * 32 + nf * 8 + lcol2;
            size_t off0 = (size_t)gr0 * M_DIM + gc;
            size_t off1 = off0 + (size_t)8 * M_DIM;
            float2 rv0 = *(const float2*)(rating + off0);
            float2 mv0 = *(const float2*)(mask + off0);
            float2 rv1 = *(const float2*)(rating + off1);
            float2 mv1 = *(const float2*)(mask + off1);
            float d0 = rv0.x - acc[mf][nf][0];
            float d1 = rv0.y - acc[mf][nf][1];
            float d2 = rv1.x - acc[mf][nf][2];
            float d3 = rv1.y - acc[mf][nf][3];
            loss += d0 * d0 * mv0.x;
            loss += d1 * d1 * mv0.y;
            loss += d2 * d2 * mv1.x;
            loss += d3 * d3 * mv1.y;
        }
    }
#pragma unroll
    for (int o = 16; o; o >>= 1) loss += __shfl_xor_sync(0xffffffffu, loss, o);
    __shared__ float red[8];
    if (lane == 0) red[wid] = loss;
    __syncthreads();
    if (tid == 0) {
        float s = 0.f;
#pragma unroll
        for (int w = 0; w < 8; ++w) s += red[w];
        atomicAdd(&g_acc, (double)s);
    }
}

// -------- finalize --------
__global__ void finalize_kernel(float* out) { out[0] = (float)g_acc; }

extern "C" void kernel_launch(void* const* d_in, const int* in_sizes, int n_in,
                              void* d_out, int out_size) {
    const float* rating = (const float*)d_in[0];
    const float* u_mat = (const float*)d_in[1];
    const float* i_mat = (const float*)d_in[2];
    const float* mask = (const float*)d_in[3];
    float* out = (float*)d_out;

    cudaFuncSetAttribute(pmf_main, cudaFuncAttributeMaxDynamicSharedMemorySize,
                         SMEM_TOTAL);

    init_kernel<<<1, 1>>>();
    conv_kernel<<<(N_DIM + M_DIM) / 8, 256>>>(u_mat, i_mat);

    dim3 grid(M_DIM / BN, N_DIM / BM);  // 128 x 64 = 8192 CTAs
    pmf_main<<<grid, THREADS, SMEM_TOTAL>>>(rating, mask);

    finalize_kernel<<<1, 1>>>(out);
}